// round 16
// baseline (speedup 1.0000x reference)
#include <cuda_runtime.h>
#include <cuda_fp16.h>
#include <math.h>

#define NN   50000
#define NE   800000      // real edges (self-loops handled implicitly)
#define NG   512
#define NH   8
#define NBLK 49          // ceil(NN/1024)

#define CNT_BLOCKS  ((NE + 255) / 256)     // 3125
#define G1_BLOCKS   ((NN + 255) / 256)     // 196

// ---------------- scratch (device globals; no allocation allowed) ----------
__device__ __align__(16) __half g_hh[NN * 128];  // fp16 feature cache for gather
__device__ float g_out [NN * 128];   // aggregated layer output / next input (fp32)
__device__ float g_es  [NN * NH];
__device__ float g_ed  [NN * NH];
__device__ int   g_deg [NN];         // zero at rest; count up then sub back to 0
__device__ int   g_off [NN + 1];     // CSR offsets (real edges only)
__device__ int   g_csr [NE];         // src node per dst-sorted edge
__device__ int   g_bsum[NBLK];
__device__ unsigned g_scan_arrive;   // zero at rest (self-resetting)
__device__ unsigned g_scan_arrive2;  // zero at rest (self-resetting)
__device__ unsigned g_scan_done;     // zero at rest (self-resetting)

struct alignas(16) H8 { __half2 a, b, c, d; };

__device__ __forceinline__ unsigned f2tf32(float f) {
    unsigned r;
    asm("cvt.rna.tf32.f32 %0, %1;" : "=r"(r) : "f"(f));
    return r;
}

__device__ __forceinline__ void mma_tf32(float c[4], unsigned a0, unsigned a1,
                                         unsigned a2, unsigned a3,
                                         unsigned b0, unsigned b1) {
    asm volatile(
        "mma.sync.aligned.m16n8k8.row.col.f32.tf32.tf32.f32 "
        "{%0,%1,%2,%3}, {%4,%5,%6,%7}, {%8,%9}, {%0,%1,%2,%3};"
        : "+f"(c[0]), "+f"(c[1]), "+f"(c[2]), "+f"(c[3])
        : "r"(a0), "r"(a1), "r"(a2), "r"(a3), "r"(b0), "r"(b1));
}

// ------- fused: degree count (blocks 0..3124) + layer-1 GEMM/attn (rest) ----
__global__ void k_count_gemm1(const int* __restrict__ ei,
                              const float* __restrict__ x, const float* __restrict__ W,
                              const float* __restrict__ aS, const float* __restrict__ aD) {
    if (blockIdx.x < CNT_BLOCKS) {
        int e = blockIdx.x * 256 + threadIdx.x;
        if (e < NE) atomicAdd(&g_deg[ei[NE + e]], 1);
        return;
    }
    __shared__ float w[128], sa[64], sd[64];
    int t0 = threadIdx.x;
    if (t0 < 128) w[t0] = W[t0];
    if (t0 >= 128 && t0 < 192) sa[t0 - 128] = aS[t0 - 128];
    if (t0 >= 192) sd[t0 - 192] = aD[t0 - 192];
    __syncthreads();
    int n = (blockIdx.x - CNT_BLOCKS) * 256 + t0;
    if (n >= NN) return;
    float x0 = x[2 * n], x1 = x[2 * n + 1];
    float out[64];
#pragma unroll
    for (int j = 0; j < 64; j++) out[j] = x0 * w[j] + x1 * w[64 + j];
#pragma unroll
    for (int h = 0; h < NH; h++) {
        float es = 0.f, ed = 0.f;
#pragma unroll
        for (int c = 0; c < 8; c++) {
            es += out[h * 8 + c] * sa[h * 8 + c];
            ed += out[h * 8 + c] * sd[h * 8 + c];
        }
        g_es[n * NH + h] = es;
        g_ed[n * NH + h] = ed;
    }
#pragma unroll
    for (int j0 = 0; j0 < 64; j0 += 8) {
        H8 p;
        p.a = __floats2half2_rn(out[j0 + 0], out[j0 + 1]);
        p.b = __floats2half2_rn(out[j0 + 2], out[j0 + 3]);
        p.c = __floats2half2_rn(out[j0 + 4], out[j0 + 5]);
        p.d = __floats2half2_rn(out[j0 + 6], out[j0 + 7]);
        *(H8*)(g_hh + n * 64 + j0) = p;
    }
}

// ---- single-kernel exclusive scan + CSR fill (49 co-resident blocks) -------
__global__ void k_scan_fill(const int* __restrict__ ei) {
    __shared__ int sh[1024];
    __shared__ int pre_s;
    int t = threadIdx.x, b = blockIdx.x;
    int idx = b * 1024 + t;
    int v = (idx < NN) ? g_deg[idx] : 0;
    sh[t] = v;
    __syncthreads();
    for (int o = 1; o < 1024; o <<= 1) {
        int add = (t >= o) ? sh[t - o] : 0;
        __syncthreads();
        sh[t] += add;
        __syncthreads();
    }
    int lv = sh[t] - v;                 // local exclusive
    if (t == 1023) {
        g_bsum[b] = sh[1023];
        __threadfence();
        atomicAdd(&g_scan_arrive, 1);
    }
    if (t == 0) {
        while (atomicAdd(&g_scan_arrive, 0) < NBLK) {}
        __threadfence();
    }
    __syncthreads();
    if (t < 64) sh[t] = (t < b && t < NBLK) ? g_bsum[t] : 0;
    __syncthreads();
    if (t == 0) {
        int s = 0;
        for (int i = 0; i < 64; i++) s += sh[i];
        pre_s = s;
    }
    __syncthreads();
    if (idx < NN) g_off[idx] = lv + pre_s;
    if (b == NBLK - 1 && t == 0) g_off[NN] = pre_s + g_bsum[b];

    // grid barrier #2: all g_off visible before fill reads them
    __threadfence();
    __syncthreads();
    if (t == 0) atomicAdd(&g_scan_arrive2, 1);
    if (t == 0) { while (atomicAdd(&g_scan_arrive2, 0) < NBLK) {} __threadfence(); }
    __syncthreads();

    // fill: strided over all edges; atomicSub restores g_deg to zero
    for (int e = b * 1024 + t; e < NE; e += NBLK * 1024) {
        int s = ei[e], d = ei[NE + e];
        int pos = atomicSub(&g_deg[d], 1) - 1;
        g_csr[g_off[d] + pos] = s;
    }

    // self-reset for graph replay
    __syncthreads();
    if (t == 0) {
        unsigned done = atomicAdd(&g_scan_done, 1);
        if (done == NBLK - 1) { g_scan_arrive = 0; g_scan_arrive2 = 0; g_scan_done = 0; }
    }
}

// ------- tensor-core GEMM (tf32) + attn epilogue: X[NN,IN] @ W[IN,128] ------
// block tile 64(M) x 128(N), 8 warps as 2(M) x 4(N), warp tile 32x32.
// Operand fragments hoisted: per k8 step B loaded ONCE (8 LDS) and A once
// (8 LDS) for 8 MMAs -> 2 LDS/MMA (was 3).
template<int IN>
__global__ void __launch_bounds__(256) k_gemm_tc(const float* __restrict__ W,
                        const float* __restrict__ aS, const float* __restrict__ aD) {
    __shared__ unsigned sA[64][36];    // m-major, k minor (pad 32->36)
    __shared__ unsigned sB[32][136];   // k-major, n minor (pad 128->136)
    const float* X = g_out;
    int bm = blockIdx.x * 64;
    int tid = threadIdx.x;
    int warp = tid >> 5, lane = tid & 31;
    int wy = warp >> 2, wx = warp & 3;
    int mw = wy * 32, nw = wx * 32;
    int g = lane >> 2, tig = lane & 3;

    float acc[2][4][4] = {};

    for (int k0 = 0; k0 < IN; k0 += 32) {
        {   // A: 64 x 32, thread loads 8 floats of one row
            int m = tid >> 2, kq = (tid & 3) * 8;
            int gm = bm + m;
            float4 v0, v1;
            if (gm < NN) {
                v0 = *(const float4*)(X + gm * IN + k0 + kq);
                v1 = *(const float4*)(X + gm * IN + k0 + kq + 4);
            } else {
                v0 = make_float4(0.f, 0.f, 0.f, 0.f); v1 = v0;
            }
            unsigned* dst = &sA[m][kq];
            dst[0] = f2tf32(v0.x); dst[1] = f2tf32(v0.y);
            dst[2] = f2tf32(v0.z); dst[3] = f2tf32(v0.w);
            dst[4] = f2tf32(v1.x); dst[5] = f2tf32(v1.y);
            dst[6] = f2tf32(v1.z); dst[7] = f2tf32(v1.w);
        }
        {   // B: 32 x 128, thread loads 16 floats of one k row
            int k = tid >> 3, c = (tid & 7) * 16;
            const float* src = W + (k0 + k) * 128 + c;
            unsigned* dst = &sB[k][c];
#pragma unroll
            for (int q = 0; q < 4; q++) {
                float4 v = *(const float4*)(src + q * 4);
                dst[q * 4 + 0] = f2tf32(v.x); dst[q * 4 + 1] = f2tf32(v.y);
                dst[q * 4 + 2] = f2tf32(v.z); dst[q * 4 + 3] = f2tf32(v.w);
            }
        }
        __syncthreads();
#pragma unroll
        for (int k8 = 0; k8 < 32; k8 += 8) {
            unsigned bf[4][2];
#pragma unroll
            for (int j = 0; j < 4; j++) {
                bf[j][0] = sB[k8 + tig][nw + j * 8 + g];
                bf[j][1] = sB[k8 + tig + 4][nw + j * 8 + g];
            }
            unsigned af[2][4];
#pragma unroll
            for (int i = 0; i < 2; i++) {
                af[i][0] = sA[mw + i * 16 + g][k8 + tig];
                af[i][1] = sA[mw + i * 16 + g + 8][k8 + tig];
                af[i][2] = sA[mw + i * 16 + g][k8 + tig + 4];
                af[i][3] = sA[mw + i * 16 + g + 8][k8 + tig + 4];
            }
#pragma unroll
            for (int i = 0; i < 2; i++)
#pragma unroll
                for (int j = 0; j < 4; j++)
                    mma_tf32(acc[i][j], af[i][0], af[i][1], af[i][2], af[i][3],
                             bf[j][0], bf[j][1]);
        }
        __syncthreads();
    }

    // epilogue: fp16 feature store + attention logits
    int hA = wx * 2, hB = wx * 2 + 1;
    float asA[4], adA[4], asB[4], adB[4];
#pragma unroll
    for (int q = 0; q < 2; q++) {
        asA[q * 2 + 0] = aS[hA * 16 + q * 8 + 2 * tig];
        asA[q * 2 + 1] = aS[hA * 16 + q * 8 + 2 * tig + 1];
        adA[q * 2 + 0] = aD[hA * 16 + q * 8 + 2 * tig];
        adA[q * 2 + 1] = aD[hA * 16 + q * 8 + 2 * tig + 1];
        asB[q * 2 + 0] = aS[hB * 16 + q * 8 + 2 * tig];
        asB[q * 2 + 1] = aS[hB * 16 + q * 8 + 2 * tig + 1];
        adB[q * 2 + 0] = aD[hB * 16 + q * 8 + 2 * tig];
        adB[q * 2 + 1] = aD[hB * 16 + q * 8 + 2 * tig + 1];
    }
#pragma unroll
    for (int i = 0; i < 2; i++) {
        int gm0 = bm + mw + i * 16 + g;
        int gm1 = gm0 + 8;
        if (gm0 < NN) {
#pragma unroll
            for (int j = 0; j < 4; j++)
                *(__half2*)(g_hh + gm0 * 128 + nw + j * 8 + 2 * tig) =
                    __floats2half2_rn(acc[i][j][0], acc[i][j][1]);
        }
        if (gm1 < NN) {
#pragma unroll
            for (int j = 0; j < 4; j++)
                *(__half2*)(g_hh + gm1 * 128 + nw + j * 8 + 2 * tig) =
                    __floats2half2_rn(acc[i][j][2], acc[i][j][3]);
        }
        float esA0 = acc[i][0][0]*asA[0] + acc[i][0][1]*asA[1] + acc[i][1][0]*asA[2] + acc[i][1][1]*asA[3];
        float edA0 = acc[i][0][0]*adA[0] + acc[i][0][1]*adA[1] + acc[i][1][0]*adA[2] + acc[i][1][1]*adA[3];
        float esB0 = acc[i][2][0]*asB[0] + acc[i][2][1]*asB[1] + acc[i][3][0]*asB[2] + acc[i][3][1]*asB[3];
        float edB0 = acc[i][2][0]*adB[0] + acc[i][2][1]*adB[1] + acc[i][3][0]*adB[2] + acc[i][3][1]*adB[3];
        float esA1 = acc[i][0][2]*asA[0] + acc[i][0][3]*asA[1] + acc[i][1][2]*asA[2] + acc[i][1][3]*asA[3];
        float edA1 = acc[i][0][2]*adA[0] + acc[i][0][3]*adA[1] + acc[i][1][2]*adA[2] + acc[i][1][3]*adA[3];
        float esB1 = acc[i][2][2]*asB[0] + acc[i][2][3]*asB[1] + acc[i][3][2]*asB[2] + acc[i][3][3]*asB[3];
        float edB1 = acc[i][2][2]*adB[0] + acc[i][2][3]*adB[1] + acc[i][3][2]*adB[2] + acc[i][3][3]*adB[3];
#pragma unroll
        for (int o = 1; o <= 2; o <<= 1) {
            esA0 += __shfl_xor_sync(0xffffffffu, esA0, o);
            edA0 += __shfl_xor_sync(0xffffffffu, edA0, o);
            esB0 += __shfl_xor_sync(0xffffffffu, esB0, o);
            edB0 += __shfl_xor_sync(0xffffffffu, edB0, o);
            esA1 += __shfl_xor_sync(0xffffffffu, esA1, o);
            edA1 += __shfl_xor_sync(0xffffffffu, edA1, o);
            esB1 += __shfl_xor_sync(0xffffffffu, esB1, o);
            edB1 += __shfl_xor_sync(0xffffffffu, edB1, o);
        }
        if (tig == 0) {
            if (gm0 < NN) {
                g_es[gm0 * NH + hA] = esA0; g_ed[gm0 * NH + hA] = edA0;
                g_es[gm0 * NH + hB] = esB0; g_ed[gm0 * NH + hB] = edB0;
            }
            if (gm1 < NN) {
                g_es[gm1 * NH + hA] = esA1; g_ed[gm1 * NH + hA] = edA1;
                g_es[gm1 * NH + hB] = esB1; g_ed[gm1 * NH + hB] = edB1;
            }
        }
    }
}

// ------ fused CSR aggregation: 2 warps/block, 4 groups x 8 lanes, 2-deep ----
// warp = 1 dst node; grp = lane>>3 walks TWO edges per iter (i, i+4; stride 8)
// lane l = lane&7 owns head l's C channels. Implicit self-loop in group 0.
template<int C, bool DO_ELU>
__global__ void k_aggr(const float* __restrict__ bias) {
    constexpr int OUT = NH * C;       // 64 or 128
    int lane = threadIdx.x & 31;
    int grp = lane >> 3, l = lane & 7;
    int d = blockIdx.x * 2 + (threadIdx.x >> 5);

    float edl = g_ed[d * NH + l];
    int beg = g_off[d], end = g_off[d + 1];

    float ssum = 0.f;
    float acc[C];
#pragma unroll
    for (int c = 0; c < C; c++) acc[c] = 0.f;

    auto process = [&](int s, float es) {
        float v = es + edl;
        v = v > 0.f ? v : 0.2f * v;
        float w = __expf(v);
        ssum += w;
        const __half* row = g_hh + s * OUT + l * C;
        if (C == 16) {
            uint4 r0 = *(const uint4*)row;
            uint4 r1 = *(const uint4*)(row + 8);
            float2 f0 = __half22float2(*(const __half2*)&r0.x);
            float2 f1 = __half22float2(*(const __half2*)&r0.y);
            float2 f2 = __half22float2(*(const __half2*)&r0.z);
            float2 f3 = __half22float2(*(const __half2*)&r0.w);
            float2 f4 = __half22float2(*(const __half2*)&r1.x);
            float2 f5 = __half22float2(*(const __half2*)&r1.y);
            float2 f6 = __half22float2(*(const __half2*)&r1.z);
            float2 f7 = __half22float2(*(const __half2*)&r1.w);
            float fv[16] = {f0.x, f0.y, f1.x, f1.y, f2.x, f2.y, f3.x, f3.y,
                            f4.x, f4.y, f5.x, f5.y, f6.x, f6.y, f7.x, f7.y};
#pragma unroll
            for (int c = 0; c < 16; c++) acc[c] += w * fv[c];
        } else {
            uint4 r0 = *(const uint4*)row;
            float2 f0 = __half22float2(*(const __half2*)&r0.x);
            float2 f1 = __half22float2(*(const __half2*)&r0.y);
            float2 f2 = __half22float2(*(const __half2*)&r0.z);
            float2 f3 = __half22float2(*(const __half2*)&r0.w);
            float fv[8] = {f0.x, f0.y, f1.x, f1.y, f2.x, f2.y, f3.x, f3.y};
#pragma unroll
            for (int c = 0; c < 8; c++) acc[c] += w * fv[c];
        }
    };

    // group 0: implicit self-loop
    if (grp == 0) process(d, g_es[d * NH + l]);

    // two edge slots in flight per group (i, i+4), stride 8
    int i = beg + grp;
    int sA = 0, sB = 0; float eA = 0.f, eB = 0.f;
    bool hasA = i < end, hasB = (i + 4) < end;
    if (hasA) { sA = __ldg(&g_csr[i]);     eA = __ldg(&g_es[sA * NH + l]); }
    if (hasB) { sB = __ldg(&g_csr[i + 4]); eB = __ldg(&g_es[sB * NH + l]); }
    while (hasA) {
        int i2 = i + 8;
        int sA2 = 0, sB2 = 0; float eA2 = 0.f, eB2 = 0.f;
        bool hA2 = i2 < end, hB2 = (i2 + 4) < end;
        if (hA2) { sA2 = __ldg(&g_csr[i2]);     eA2 = __ldg(&g_es[sA2 * NH + l]); }
        if (hB2) { sB2 = __ldg(&g_csr[i2 + 4]); eB2 = __ldg(&g_es[sB2 * NH + l]); }
        process(sA, eA);
        if (hasB) process(sB, eB);
        sA = sA2; eA = eA2; sB = sB2; eB = eB2;
        hasA = hA2; hasB = hB2; i = i2;
    }

    // merge the 4 groups: plain sums (xor 8, 16)
#pragma unroll
    for (int o = 8; o <= 16; o <<= 1) {
        ssum += __shfl_xor_sync(0xffffffffu, ssum, o);
#pragma unroll
        for (int c = 0; c < C; c++)
            acc[c] += __shfl_xor_sync(0xffffffffu, acc[c], o);
    }

    if (grp == 0) {
        float inv = 1.f / (ssum + 1e-16f);
        float* op = g_out + d * OUT + l * C;
#pragma unroll
        for (int c4 = 0; c4 < C / 4; c4++) {
            float4 o4;
            float* oc = (float*)&o4;
#pragma unroll
            for (int k = 0; k < 4; k++) {
                float v = acc[c4 * 4 + k] * inv + bias[l * C + c4 * 4 + k];
                if (DO_ELU) v = v > 0.f ? v : expm1f(v);
                oc[k] = v;
            }
            *(float4*)(op + c4 * 4) = o4;
        }
    }
}

// ------ head: segmented mean pool (batch sorted) + fc1 + fc2 + log_softmax --
__global__ void k_mlp(const int* __restrict__ batch,
                      const float* __restrict__ fc1W, const float* __restrict__ fc1b,
                      const float* __restrict__ fc2W, const float* __restrict__ fc2b,
                      float* __restrict__ out) {
    __shared__ int bounds[2];
    __shared__ float p[128];
    __shared__ float z[32];
    __shared__ float y[10];
    __shared__ float red[2];
    int g = blockIdx.x, t = threadIdx.x;
    if (t < 2) {
        int key = g + t;
        int lo = 0, hi = NN;
        while (lo < hi) {
            int mid = (lo + hi) >> 1;
            if (batch[mid] < key) lo = mid + 1; else hi = mid;
        }
        bounds[t] = lo;
    }
    __syncthreads();
    int beg = bounds[0], end = bounds[1];
    float s0 = 0.f, s1 = 0.f, s2 = 0.f, s3 = 0.f;
    int n = beg;
    for (; n + 4 <= end; n += 4) {
        s0 += g_out[(n + 0) * 128 + t];
        s1 += g_out[(n + 1) * 128 + t];
        s2 += g_out[(n + 2) * 128 + t];
        s3 += g_out[(n + 3) * 128 + t];
    }
    for (; n < end; n++) s0 += g_out[n * 128 + t];
    float inv = 1.f / fmaxf((float)(end - beg), 1.f);
    p[t] = (s0 + s1 + s2 + s3) * inv;
    __syncthreads();
    if (t < 32) {
        float a = fc1b[t];
        for (int c = 0; c < 128; c++) a += p[c] * fc1W[c * 32 + t];
        z[t] = fmaxf(a, 0.f);
    }
    __syncthreads();
    if (t < 10) {
        float a = fc2b[t];
        for (int j = 0; j < 32; j++) a += z[j] * fc2W[j * 10 + t];
        y[t] = a;
    }
    __syncthreads();
    if (t == 0) {
        float mx = y[0];
        for (int k = 1; k < 10; k++) mx = fmaxf(mx, y[k]);
        float ssum = 0.f;
        for (int k = 0; k < 10; k++) ssum += expf(y[k] - mx);
        red[0] = mx; red[1] = logf(ssum);
    }
    __syncthreads();
    if (t < 10) out[g * 10 + t] = y[t] - red[0] - red[1];
}

// ---------------- host driver ----------------------------------------------
extern "C" void kernel_launch(void* const* d_in, const int* in_sizes, int n_in,
                              void* d_out, int out_size) {
    const float* x     = (const float*)d_in[0];
    const int*   ei    = (const int*)  d_in[1];
    const int*   batch = (const int*)  d_in[2];
    const float* W1  = (const float*)d_in[3];
    const float* a1s = (const float*)d_in[4];
    const float* a1d = (const float*)d_in[5];
    const float* b1  = (const float*)d_in[6];
    const float* W2  = (const float*)d_in[7];
    const float* a2s = (const float*)d_in[8];
    const float* a2d = (const float*)d_in[9];
    const float* b2  = (const float*)d_in[10];
    const float* W3  = (const float*)d_in[11];
    const float* a3s = (const float*)d_in[12];
    const float* a3d = (const float*)d_in[13];
    const float* b3  = (const float*)d_in[14];
    const float* fc1W = (const float*)d_in[15];
    const float* fc1b = (const float*)d_in[16];
    const float* fc2W = (const float*)d_in[17];
    const float* fc2b = (const float*)d_in[18];

    // ---- fused: degree count + layer-1 GEMM/attn (independent work) ----
    k_count_gemm1<<<CNT_BLOCKS + G1_BLOCKS, 256>>>(ei, x, W1, a1s, a1d);
    // ---- CSR: single-kernel scan + fill (grid barriers inside) ----
    k_scan_fill<<<NBLK, 1024>>>(ei);

    int aggr_grid = NN / 2;           // 25000, 2 warps per block
    int gemm_grid = (NN + 63) / 64;

    // ---- layer 1 aggregation: C=8, OUT=64, ELU ----
    k_aggr<8, true><<<aggr_grid, 64>>>(b1);

    // ---- layer 2: IN=64, OUT=128, ELU ----
    k_gemm_tc<64><<<gemm_grid, 256>>>(W2, a2s, a2d);
    k_aggr<16, true><<<aggr_grid, 64>>>(b2);

    // ---- layer 3: IN=128, OUT=128, no ELU ----
    k_gemm_tc<128><<<gemm_grid, 256>>>(W3, a3s, a3d);
    k_aggr<16, false><<<aggr_grid, 64>>>(b3);

    k_mlp<<<NG, 128>>>(batch, fc1W, fc1b, fc2W, fc2b, (float*)d_out);
}

// round 17
// speedup vs baseline: 1.0531x; 1.0531x over previous
#include <cuda_runtime.h>
#include <cuda_fp16.h>
#include <math.h>

#define NN   50000
#define NE   800000      // real edges (self-loops handled implicitly)
#define NG   512
#define NH   8
#define NBLK 49          // ceil(NN/1024)

#define CNT_BLOCKS  ((NE + 255) / 256)     // 3125
#define G1_BLOCKS   ((NN + 255) / 256)     // 196

// ---------------- scratch (device globals; no allocation allowed) ----------
__device__ __align__(16) __half g_hh[NN * 128];  // fp16 feature cache for gather
__device__ float g_out [NN * 128];   // aggregated layer output / next input (fp32)
__device__ float g_es  [NN * NH];
__device__ float g_ed  [NN * NH];
__device__ int   g_deg [NN];         // zero at rest; count up then sub back to 0
__device__ int   g_off [NN + 1];     // CSR offsets (real edges only)
__device__ int   g_csr [NE];         // src node per dst-sorted edge
__device__ int   g_bsum[NBLK];
__device__ unsigned g_scan_arrive;   // zero at rest (self-resetting)
__device__ unsigned g_scan_done;     // zero at rest (self-resetting)

struct alignas(16) H8 { __half2 a, b, c, d; };

__device__ __forceinline__ unsigned f2tf32(float f) {
    unsigned r;
    asm("cvt.rna.tf32.f32 %0, %1;" : "=r"(r) : "f"(f));
    return r;
}

__device__ __forceinline__ void mma_tf32(float c[4], unsigned a0, unsigned a1,
                                         unsigned a2, unsigned a3,
                                         unsigned b0, unsigned b1) {
    asm volatile(
        "mma.sync.aligned.m16n8k8.row.col.f32.tf32.tf32.f32 "
        "{%0,%1,%2,%3}, {%4,%5,%6,%7}, {%8,%9}, {%0,%1,%2,%3};"
        : "+f"(c[0]), "+f"(c[1]), "+f"(c[2]), "+f"(c[3])
        : "r"(a0), "r"(a1), "r"(a2), "r"(a3), "r"(b0), "r"(b1));
}

// ------- fused: degree count (blocks 0..3124) + layer-1 GEMM/attn (rest) ----
__global__ void k_count_gemm1(const int* __restrict__ ei,
                              const float* __restrict__ x, const float* __restrict__ W,
                              const float* __restrict__ aS, const float* __restrict__ aD) {
    if (blockIdx.x < CNT_BLOCKS) {
        int e = blockIdx.x * 256 + threadIdx.x;
        if (e < NE) atomicAdd(&g_deg[ei[NE + e]], 1);
        return;
    }
    __shared__ float w[128], sa[64], sd[64];
    int t0 = threadIdx.x;
    if (t0 < 128) w[t0] = W[t0];
    if (t0 >= 128 && t0 < 192) sa[t0 - 128] = aS[t0 - 128];
    if (t0 >= 192) sd[t0 - 192] = aD[t0 - 192];
    __syncthreads();
    int n = (blockIdx.x - CNT_BLOCKS) * 256 + t0;
    if (n >= NN) return;
    float x0 = x[2 * n], x1 = x[2 * n + 1];
    float out[64];
#pragma unroll
    for (int j = 0; j < 64; j++) out[j] = x0 * w[j] + x1 * w[64 + j];
#pragma unroll
    for (int h = 0; h < NH; h++) {
        float es = 0.f, ed = 0.f;
#pragma unroll
        for (int c = 0; c < 8; c++) {
            es += out[h * 8 + c] * sa[h * 8 + c];
            ed += out[h * 8 + c] * sd[h * 8 + c];
        }
        g_es[n * NH + h] = es;
        g_ed[n * NH + h] = ed;
    }
#pragma unroll
    for (int j0 = 0; j0 < 64; j0 += 8) {
        H8 p;
        p.a = __floats2half2_rn(out[j0 + 0], out[j0 + 1]);
        p.b = __floats2half2_rn(out[j0 + 2], out[j0 + 3]);
        p.c = __floats2half2_rn(out[j0 + 4], out[j0 + 5]);
        p.d = __floats2half2_rn(out[j0 + 6], out[j0 + 7]);
        *(H8*)(g_hh + n * 64 + j0) = p;
    }
}

// ---------- single-kernel exclusive scan (49 co-resident blocks) ------------
__global__ void k_scan() {
    __shared__ int sh[1024];
    __shared__ int pre_s;
    int t = threadIdx.x, b = blockIdx.x;
    int idx = b * 1024 + t;
    int v = (idx < NN) ? g_deg[idx] : 0;
    sh[t] = v;
    __syncthreads();
    for (int o = 1; o < 1024; o <<= 1) {
        int add = (t >= o) ? sh[t - o] : 0;
        __syncthreads();
        sh[t] += add;
        __syncthreads();
    }
    int lv = sh[t] - v;                 // local exclusive
    if (t == 1023) {
        g_bsum[b] = sh[1023];
        __threadfence();
        atomicAdd(&g_scan_arrive, 1);
    }
    if (t == 0) {
        while (atomicAdd(&g_scan_arrive, 0) < NBLK) {}
        __threadfence();
    }
    __syncthreads();
    if (t < 64) sh[t] = (t < b && t < NBLK) ? g_bsum[t] : 0;
    __syncthreads();
    if (t == 0) {
        int s = 0;
        for (int i = 0; i < 64; i++) s += sh[i];
        pre_s = s;
    }
    __syncthreads();
    if (idx < NN) g_off[idx] = lv + pre_s;
    if (b == NBLK - 1 && t == 0) g_off[NN] = pre_s + g_bsum[b];
    if (t == 0) {
        unsigned done = atomicAdd(&g_scan_done, 1);
        if (done == NBLK - 1) { g_scan_arrive = 0; g_scan_done = 0; }
    }
}

// fill using atomicSub on counts (restores g_deg to all-zero)
__global__ void k_fill(const int* __restrict__ ei) {
    int e = blockIdx.x * blockDim.x + threadIdx.x;
    if (e >= NE) return;
    int s = ei[e], d = ei[NE + e];
    int pos = atomicSub(&g_deg[d], 1) - 1;
    g_csr[g_off[d] + pos] = s;
}

// ------- tensor-core GEMM (tf32) + attn epilogue: X[NN,IN] @ W[IN,128] ------
// block tile 64(M) x 128(N), 8 warps as 2(M) x 4(N), warp tile 32x32.
// A double-buffered in smem; A and B register-staged so next chunk's LDG
// overlaps current chunk's MMAs. Fragments hoisted (2 LDS/MMA).
template<int IN>
__global__ void __launch_bounds__(256) k_gemm_tc(const float* __restrict__ W,
                        const float* __restrict__ aS, const float* __restrict__ aD) {
    __shared__ unsigned sA[2][64][36];   // m-major, k minor (pad 32->36)
    __shared__ unsigned sB[32][136];     // k-major, n minor (pad 128->136)
    constexpr int STEPS = IN / 32;
    const float* X = g_out;
    int bm = blockIdx.x * 64;
    int tid = threadIdx.x;
    int warp = tid >> 5, lane = tid & 31;
    int wy = warp >> 2, wx = warp & 3;
    int mw = wy * 32, nw = wx * 32;
    int g = lane >> 2, tig = lane & 3;

    int am = tid >> 2, akq = (tid & 3) * 8;   // A staging: row am, k-quad akq
    int bk = tid >> 3, bc = (tid & 7) * 16;   // B staging: k row bk, col bc

    float4 av0, av1, bv0, bv1, bv2, bv3;
    auto ldg = [&](int k0) {
        int gm = bm + am;
        if (gm < NN) {
            av0 = *(const float4*)(X + gm * IN + k0 + akq);
            av1 = *(const float4*)(X + gm * IN + k0 + akq + 4);
        } else {
            av0 = make_float4(0.f, 0.f, 0.f, 0.f); av1 = av0;
        }
        const float* src = W + (k0 + bk) * 128 + bc;
        bv0 = *(const float4*)(src);
        bv1 = *(const float4*)(src + 4);
        bv2 = *(const float4*)(src + 8);
        bv3 = *(const float4*)(src + 12);
    };
    auto sts = [&](int buf) {
        unsigned* dA = &sA[buf][am][akq];
        dA[0] = f2tf32(av0.x); dA[1] = f2tf32(av0.y);
        dA[2] = f2tf32(av0.z); dA[3] = f2tf32(av0.w);
        dA[4] = f2tf32(av1.x); dA[5] = f2tf32(av1.y);
        dA[6] = f2tf32(av1.z); dA[7] = f2tf32(av1.w);
        unsigned* dB = &sB[bk][bc];
        dB[0]  = f2tf32(bv0.x); dB[1]  = f2tf32(bv0.y);
        dB[2]  = f2tf32(bv0.z); dB[3]  = f2tf32(bv0.w);
        dB[4]  = f2tf32(bv1.x); dB[5]  = f2tf32(bv1.y);
        dB[6]  = f2tf32(bv1.z); dB[7]  = f2tf32(bv1.w);
        dB[8]  = f2tf32(bv2.x); dB[9]  = f2tf32(bv2.y);
        dB[10] = f2tf32(bv2.z); dB[11] = f2tf32(bv2.w);
        dB[12] = f2tf32(bv3.x); dB[13] = f2tf32(bv3.y);
        dB[14] = f2tf32(bv3.z); dB[15] = f2tf32(bv3.w);
    };

    float acc[2][4][4] = {};

    ldg(0);
    sts(0);
    __syncthreads();
#pragma unroll
    for (int s = 0; s < STEPS; s++) {
        if (s + 1 < STEPS) ldg((s + 1) * 32);   // prefetch next chunk (overlaps MMAs)
        int cur = s & 1;
#pragma unroll
        for (int k8 = 0; k8 < 32; k8 += 8) {
            unsigned bf[4][2];
#pragma unroll
            for (int j = 0; j < 4; j++) {
                bf[j][0] = sB[k8 + tig][nw + j * 8 + g];
                bf[j][1] = sB[k8 + tig + 4][nw + j * 8 + g];
            }
            unsigned af[2][4];
#pragma unroll
            for (int i = 0; i < 2; i++) {
                af[i][0] = sA[cur][mw + i * 16 + g][k8 + tig];
                af[i][1] = sA[cur][mw + i * 16 + g + 8][k8 + tig];
                af[i][2] = sA[cur][mw + i * 16 + g][k8 + tig + 4];
                af[i][3] = sA[cur][mw + i * 16 + g + 8][k8 + tig + 4];
            }
#pragma unroll
            for (int i = 0; i < 2; i++)
#pragma unroll
                for (int j = 0; j < 4; j++)
                    mma_tf32(acc[i][j], af[i][0], af[i][1], af[i][2], af[i][3],
                             bf[j][0], bf[j][1]);
        }
        if (s + 1 < STEPS) {
            __syncthreads();          // all reads of sB done before overwrite
            sts((s + 1) & 1);
            __syncthreads();          // new tiles visible
        }
    }

    // epilogue: fp16 feature store + attention logits
    int hA = wx * 2, hB = wx * 2 + 1;
    float asA[4], adA[4], asB[4], adB[4];
#pragma unroll
    for (int q = 0; q < 2; q++) {
        asA[q * 2 + 0] = aS[hA * 16 + q * 8 + 2 * tig];
        asA[q * 2 + 1] = aS[hA * 16 + q * 8 + 2 * tig + 1];
        adA[q * 2 + 0] = aD[hA * 16 + q * 8 + 2 * tig];
        adA[q * 2 + 1] = aD[hA * 16 + q * 8 + 2 * tig + 1];
        asB[q * 2 + 0] = aS[hB * 16 + q * 8 + 2 * tig];
        asB[q * 2 + 1] = aS[hB * 16 + q * 8 + 2 * tig + 1];
        adB[q * 2 + 0] = aD[hB * 16 + q * 8 + 2 * tig];
        adB[q * 2 + 1] = aD[hB * 16 + q * 8 + 2 * tig + 1];
    }
#pragma unroll
    for (int i = 0; i < 2; i++) {
        int gm0 = bm + mw + i * 16 + g;
        int gm1 = gm0 + 8;
        if (gm0 < NN) {
#pragma unroll
            for (int j = 0; j < 4; j++)
                *(__half2*)(g_hh + gm0 * 128 + nw + j * 8 + 2 * tig) =
                    __floats2half2_rn(acc[i][j][0], acc[i][j][1]);
        }
        if (gm1 < NN) {
#pragma unroll
            for (int j = 0; j < 4; j++)
                *(__half2*)(g_hh + gm1 * 128 + nw + j * 8 + 2 * tig) =
                    __floats2half2_rn(acc[i][j][2], acc[i][j][3]);
        }
        float esA0 = acc[i][0][0]*asA[0] + acc[i][0][1]*asA[1] + acc[i][1][0]*asA[2] + acc[i][1][1]*asA[3];
        float edA0 = acc[i][0][0]*adA[0] + acc[i][0][1]*adA[1] + acc[i][1][0]*adA[2] + acc[i][1][1]*adA[3];
        float esB0 = acc[i][2][0]*asB[0] + acc[i][2][1]*asB[1] + acc[i][3][0]*asB[2] + acc[i][3][1]*asB[3];
        float edB0 = acc[i][2][0]*adB[0] + acc[i][2][1]*adB[1] + acc[i][3][0]*adB[2] + acc[i][3][1]*adB[3];
        float esA1 = acc[i][0][2]*asA[0] + acc[i][0][3]*asA[1] + acc[i][1][2]*asA[2] + acc[i][1][3]*asA[3];
        float edA1 = acc[i][0][2]*adA[0] + acc[i][0][3]*adA[1] + acc[i][1][2]*adA[2] + acc[i][1][3]*adA[3];
        float esB1 = acc[i][2][2]*asB[0] + acc[i][2][3]*asB[1] + acc[i][3][2]*asB[2] + acc[i][3][3]*asB[3];
        float edB1 = acc[i][2][2]*adB[0] + acc[i][2][3]*adB[1] + acc[i][3][2]*adB[2] + acc[i][3][3]*adB[3];
#pragma unroll
        for (int o = 1; o <= 2; o <<= 1) {
            esA0 += __shfl_xor_sync(0xffffffffu, esA0, o);
            edA0 += __shfl_xor_sync(0xffffffffu, edA0, o);
            esB0 += __shfl_xor_sync(0xffffffffu, esB0, o);
            edB0 += __shfl_xor_sync(0xffffffffu, edB0, o);
            esA1 += __shfl_xor_sync(0xffffffffu, esA1, o);
            edA1 += __shfl_xor_sync(0xffffffffu, edA1, o);
            esB1 += __shfl_xor_sync(0xffffffffu, esB1, o);
            edB1 += __shfl_xor_sync(0xffffffffu, edB1, o);
        }
        if (tig == 0) {
            if (gm0 < NN) {
                g_es[gm0 * NH + hA] = esA0; g_ed[gm0 * NH + hA] = edA0;
                g_es[gm0 * NH + hB] = esB0; g_ed[gm0 * NH + hB] = edB0;
            }
            if (gm1 < NN) {
                g_es[gm1 * NH + hA] = esA1; g_ed[gm1 * NH + hA] = edA1;
                g_es[gm1 * NH + hB] = esB1; g_ed[gm1 * NH + hB] = edB1;
            }
        }
    }
}

// ------ fused CSR aggregation: 2 warps/block, 4 groups x 8 lanes, 2-deep ----
// warp = 1 dst node; grp = lane>>3 walks TWO edges per iter (i, i+4; stride 8)
// lane l = lane&7 owns head l's C channels. Implicit self-loop in group 0.
template<int C, bool DO_ELU>
__global__ void k_aggr(const float* __restrict__ bias) {
    constexpr int OUT = NH * C;       // 64 or 128
    int lane = threadIdx.x & 31;
    int grp = lane >> 3, l = lane & 7;
    int d = blockIdx.x * 2 + (threadIdx.x >> 5);

    float edl = g_ed[d * NH + l];
    int beg = g_off[d], end = g_off[d + 1];

    float ssum = 0.f;
    float acc[C];
#pragma unroll
    for (int c = 0; c < C; c++) acc[c] = 0.f;

    auto process = [&](int s, float es) {
        float v = es + edl;
        v = v > 0.f ? v : 0.2f * v;
        float w = __expf(v);
        ssum += w;
        const __half* row = g_hh + s * OUT + l * C;
        if (C == 16) {
            uint4 r0 = *(const uint4*)row;
            uint4 r1 = *(const uint4*)(row + 8);
            float2 f0 = __half22float2(*(const __half2*)&r0.x);
            float2 f1 = __half22float2(*(const __half2*)&r0.y);
            float2 f2 = __half22float2(*(const __half2*)&r0.z);
            float2 f3 = __half22float2(*(const __half2*)&r0.w);
            float2 f4 = __half22float2(*(const __half2*)&r1.x);
            float2 f5 = __half22float2(*(const __half2*)&r1.y);
            float2 f6 = __half22float2(*(const __half2*)&r1.z);
            float2 f7 = __half22float2(*(const __half2*)&r1.w);
            float fv[16] = {f0.x, f0.y, f1.x, f1.y, f2.x, f2.y, f3.x, f3.y,
                            f4.x, f4.y, f5.x, f5.y, f6.x, f6.y, f7.x, f7.y};
#pragma unroll
            for (int c = 0; c < 16; c++) acc[c] += w * fv[c];
        } else {
            uint4 r0 = *(const uint4*)row;
            float2 f0 = __half22float2(*(const __half2*)&r0.x);
            float2 f1 = __half22float2(*(const __half2*)&r0.y);
            float2 f2 = __half22float2(*(const __half2*)&r0.z);
            float2 f3 = __half22float2(*(const __half2*)&r0.w);
            float fv[8] = {f0.x, f0.y, f1.x, f1.y, f2.x, f2.y, f3.x, f3.y};
#pragma unroll
            for (int c = 0; c < 8; c++) acc[c] += w * fv[c];
        }
    };

    // group 0: implicit self-loop
    if (grp == 0) process(d, g_es[d * NH + l]);

    // two edge slots in flight per group (i, i+4), stride 8
    int i = beg + grp;
    int sA = 0, sB = 0; float eA = 0.f, eB = 0.f;
    bool hasA = i < end, hasB = (i + 4) < end;
    if (hasA) { sA = __ldg(&g_csr[i]);     eA = __ldg(&g_es[sA * NH + l]); }
    if (hasB) { sB = __ldg(&g_csr[i + 4]); eB = __ldg(&g_es[sB * NH + l]); }
    while (hasA) {
        int i2 = i + 8;
        int sA2 = 0, sB2 = 0; float eA2 = 0.f, eB2 = 0.f;
        bool hA2 = i2 < end, hB2 = (i2 + 4) < end;
        if (hA2) { sA2 = __ldg(&g_csr[i2]);     eA2 = __ldg(&g_es[sA2 * NH + l]); }
        if (hB2) { sB2 = __ldg(&g_csr[i2 + 4]); eB2 = __ldg(&g_es[sB2 * NH + l]); }
        process(sA, eA);
        if (hasB) process(sB, eB);
        sA = sA2; eA = eA2; sB = sB2; eB = eB2;
        hasA = hA2; hasB = hB2; i = i2;
    }

    // merge the 4 groups: plain sums (xor 8, 16)
#pragma unroll
    for (int o = 8; o <= 16; o <<= 1) {
        ssum += __shfl_xor_sync(0xffffffffu, ssum, o);
#pragma unroll
        for (int c = 0; c < C; c++)
            acc[c] += __shfl_xor_sync(0xffffffffu, acc[c], o);
    }

    if (grp == 0) {
        float inv = 1.f / (ssum + 1e-16f);
        float* op = g_out + d * OUT + l * C;
#pragma unroll
        for (int c4 = 0; c4 < C / 4; c4++) {
            float4 o4;
            float* oc = (float*)&o4;
#pragma unroll
            for (int k = 0; k < 4; k++) {
                float v = acc[c4 * 4 + k] * inv + bias[l * C + c4 * 4 + k];
                if (DO_ELU) v = v > 0.f ? v : expm1f(v);
                oc[k] = v;
            }
            *(float4*)(op + c4 * 4) = o4;
        }
    }
}

// ------ head: segmented mean pool (batch sorted) + fc1 + fc2 + log_softmax --
__global__ void k_mlp(const int* __restrict__ batch,
                      const float* __restrict__ fc1W, const float* __restrict__ fc1b,
                      const float* __restrict__ fc2W, const float* __restrict__ fc2b,
                      float* __restrict__ out) {
    __shared__ int bounds[2];
    __shared__ float p[128];
    __shared__ float z[32];
    __shared__ float y[10];
    __shared__ float red[2];
    int g = blockIdx.x, t = threadIdx.x;
    if (t < 2) {
        int key = g + t;
        int lo = 0, hi = NN;
        while (lo < hi) {
            int mid = (lo + hi) >> 1;
            if (batch[mid] < key) lo = mid + 1; else hi = mid;
        }
        bounds[t] = lo;
    }
    __syncthreads();
    int beg = bounds[0], end = bounds[1];
    float s0 = 0.f, s1 = 0.f, s2 = 0.f, s3 = 0.f;
    int n = beg;
    for (; n + 4 <= end; n += 4) {
        s0 += g_out[(n + 0) * 128 + t];
        s1 += g_out[(n + 1) * 128 + t];
        s2 += g_out[(n + 2) * 128 + t];
        s3 += g_out[(n + 3) * 128 + t];
    }
    for (; n < end; n++) s0 += g_out[n * 128 + t];
    float inv = 1.f / fmaxf((float)(end - beg), 1.f);
    p[t] = (s0 + s1 + s2 + s3) * inv;
    __syncthreads();
    if (t < 32) {
        float a = fc1b[t];
        for (int c = 0; c < 128; c++) a += p[c] * fc1W[c * 32 + t];
        z[t] = fmaxf(a, 0.f);
    }
    __syncthreads();
    if (t < 10) {
        float a = fc2b[t];
        for (int j = 0; j < 32; j++) a += z[j] * fc2W[j * 10 + t];
        y[t] = a;
    }
    __syncthreads();
    if (t == 0) {
        float mx = y[0];
        for (int k = 1; k < 10; k++) mx = fmaxf(mx, y[k]);
        float ssum = 0.f;
        for (int k = 0; k < 10; k++) ssum += expf(y[k] - mx);
        red[0] = mx; red[1] = logf(ssum);
    }
    __syncthreads();
    if (t < 10) out[g * 10 + t] = y[t] - red[0] - red[1];
}

// ---------------- host driver ----------------------------------------------
extern "C" void kernel_launch(void* const* d_in, const int* in_sizes, int n_in,
                              void* d_out, int out_size) {
    const float* x     = (const float*)d_in[0];
    const int*   ei    = (const int*)  d_in[1];
    const int*   batch = (const int*)  d_in[2];
    const float* W1  = (const float*)d_in[3];
    const float* a1s = (const float*)d_in[4];
    const float* a1d = (const float*)d_in[5];
    const float* b1  = (const float*)d_in[6];
    const float* W2  = (const float*)d_in[7];
    const float* a2s = (const float*)d_in[8];
    const float* a2d = (const float*)d_in[9];
    const float* b2  = (const float*)d_in[10];
    const float* W3  = (const float*)d_in[11];
    const float* a3s = (const float*)d_in[12];
    const float* a3d = (const float*)d_in[13];
    const float* b3  = (const float*)d_in[14];
    const float* fc1W = (const float*)d_in[15];
    const float* fc1b = (const float*)d_in[16];
    const float* fc2W = (const float*)d_in[17];
    const float* fc2b = (const float*)d_in[18];

    // ---- fused: degree count + layer-1 GEMM/attn (independent work) ----
    k_count_gemm1<<<CNT_BLOCKS + G1_BLOCKS, 256>>>(ei, x, W1, a1s, a1d);
    // ---- CSR: single-kernel scan, then wide fill ----
    k_scan<<<NBLK, 1024>>>();
    k_fill<<<(NE + 255) / 256, 256>>>(ei);

    int aggr_grid = NN / 2;           // 25000, 2 warps per block
    int gemm_grid = (NN + 63) / 64;

    // ---- layer 1 aggregation: C=8, OUT=64, ELU ----
    k_aggr<8, true><<<aggr_grid, 64>>>(b1);

    // ---- layer 2: IN=64, OUT=128, ELU ----
    k_gemm_tc<64><<<gemm_grid, 256>>>(W2, a2s, a2d);
    k_aggr<16, true><<<aggr_grid, 64>>>(b2);

    // ---- layer 3: IN=128, OUT=128, no ELU ----
    k_gemm_tc<128><<<gemm_grid, 256>>>(W3, a3s, a3d);
    k_aggr<16, false><<<aggr_grid, 64>>>(b3);

    k_mlp<<<NG, 128>>>(batch, fc1W, fc1b, fc2W, fc2b, (float*)d_out);
}